// round 8
// baseline (speedup 1.0000x reference)
#include <cuda_runtime.h>
#include <cuda_bf16.h>

#define FULLMASK 0xFFFFFFFFu
#define LOG2E 1.4426950408889634f

using u64 = unsigned long long;

__device__ __forceinline__ u64 fma2(u64 a, u64 b, u64 c) {
    u64 d; asm("fma.rn.f32x2 %0,%1,%2,%3;" : "=l"(d) : "l"(a), "l"(b), "l"(c)); return d;
}
__device__ __forceinline__ u64 add2(u64 a, u64 b) {
    u64 d; asm("add.rn.f32x2 %0,%1,%2;" : "=l"(d) : "l"(a), "l"(b)); return d;
}
__device__ __forceinline__ u64 bcast2(float v) {
    u64 d; asm("mov.b64 %0,{%1,%1};" : "=l"(d) : "f"(v)); return d;
}
__device__ __forceinline__ float2 unpk(u64 v) {
    float2 r; asm("mov.b64 {%0,%1},%2;" : "=f"(r.x), "=f"(r.y) : "l"(v)); return r;
}
__device__ __forceinline__ float ex2f(float x) {
    float r; asm("ex2.approx.f32 %0,%1;" : "=f"(r) : "f"(x)); return r;
}
__device__ __forceinline__ float rcpf(float x) {
    float r; asm("rcp.approx.f32 %0,%1;" : "=f"(r) : "f"(x)); return r;
}
__device__ __forceinline__ float rsqf(float x) {
    float r; asm("rsqrt.approx.f32 %0,%1;" : "=f"(r) : "f"(x)); return r;
}

union Row { ulonglong2 u; float4 f; };

// Layout: 4 locations per warp, 8 lanes per location.
// t = lane&7, h = t>>2 (row-half), q = t&3 (d-quad; quads = width-4 segments).
// Lane holds 8 rows of its half (i = 8h + r) in ROTATION ORDER:
//   slot (k,j), k=0..3, j=0..1  ->  local row r = 2*((q+k)&3) + j
// and columns d = 4q..4q+3 of each row.
// Each lane OWNS rows 8h+2q, 8h+2q+1: keeps their logits bb0/bb1 and computes
// their exponentials. Quad comm via shfl.idx (width 4), compile-time slots.
// Agree ring-reduce: partner at +k holds my rows' partials in slot (4-k)&3.
//
// b kept in log2-space; softmax normalizer 1/s never materialized (cancels in
// squash): out = a * sq * rcp(s^2+sq) * rsq(sq + eps*s^2). No max-subtract.
__global__ void __launch_bounds__(256, 5) routing_kernel(
    const float* __restrict__ pred,
    const float* __restrict__ b_in,
    const int*   __restrict__ nit,
    float*       __restrict__ out,
    int n_loc, int ohw, int ohw_mask)
{
    const int lane = threadIdx.x & 31;
    const int t = lane & 7;
    const int h = t >> 2;
    const int q = t & 3;
    const unsigned warp_id = blockIdx.x * (blockDim.x >> 5) + (threadIdx.x >> 5);
    const int g = lane >> 3;
    if (warp_id * 4u >= (unsigned)n_loc) return;
    const unsigned loc = warp_id * 4u + g;

    const int s1 = (q + 1) & 3, s2 = (q + 2) & 3, s3 = (q + 3) & 3;

    // pred tile: 8 LDG.128, rotation-ordered rows
    const ulonglong2* p4 =
        reinterpret_cast<const ulonglong2*>(pred) + (size_t)warp_id * 256;
    Row P[8];
    {
        const int base = 64 * g + 32 * h + q;
#pragma unroll
        for (int k = 0; k < 4; ++k) {
            const int off = 8 * ((q + k) & 3);
            P[2 * k].u     = p4[base + off];
            P[2 * k + 1].u = p4[base + off + 4];
        }
    }

    // logits for OWNED rows: one LDG.64 (log2-space)
    const unsigned bloc = ohw_mask ? (loc & (unsigned)ohw_mask)
                                   : (loc % (unsigned)ohw);
    float bb0, bb1;
    {
        const float2 b2 = *reinterpret_cast<const float2*>(
            b_in + (size_t)bloc * 16 + 8 * h + 2 * q);
        bb0 = b2.x * LOG2E;
        bb1 = b2.y * LOG2E;
    }

    const int iters = *nit;
    float o0, o1, o2, o3;

    auto pass = [&]() {
        // exponentials of owned rows only, quad-gather in slot order
        const float e0 = ex2f(bb0), e1 = ex2f(bb1);
        float e[8];
        e[0] = e0; e[1] = e1;
        e[2] = __shfl_sync(FULLMASK, e0, s1, 4);
        e[3] = __shfl_sync(FULLMASK, e1, s1, 4);
        e[4] = __shfl_sync(FULLMASK, e0, s2, 4);
        e[5] = __shfl_sync(FULLMASK, e1, s2, 4);
        e[6] = __shfl_sync(FULLMASK, e0, s3, 4);
        e[7] = __shfl_sync(FULLMASK, e1, s3, 4);

        float s = ((e[0] + e[1]) + (e[2] + e[3])) +
                  ((e[4] + e[5]) + (e[6] + e[7]));
        s += __shfl_xor_sync(FULLMASK, s, 4);

        // weighted sum: TWO parallel 4-deep packed chains per half
        u64 x01 = 0ull, y01 = 0ull, x23 = 0ull, y23 = 0ull;
#pragma unroll
        for (int r = 0; r < 8; r += 2) {
            const u64 ea = bcast2(e[r]);
            const u64 eb = bcast2(e[r + 1]);
            x01 = fma2(ea, P[r].u.x, x01);
            x23 = fma2(ea, P[r].u.y, x23);
            y01 = fma2(eb, P[r + 1].u.x, y01);
            y23 = fma2(eb, P[r + 1].u.y, y23);
        }
        u64 a01 = add2(x01, y01);
        u64 a23 = add2(x23, y23);
        a01 = add2(a01, __shfl_xor_sync(FULLMASK, a01, 4));
        a23 = add2(a23, __shfl_xor_sync(FULLMASK, a23, 4));

        float2 lo = unpk(a01), hi = unpk(a23);
        const float a0 = lo.x, a1 = lo.y, a2 = hi.x, a3 = hi.y;

        float sq = fmaf(a3, a3, fmaf(a2, a2, fmaf(a1, a1, a0 * a0)));
        sq += __shfl_xor_sync(FULLMASK, sq, 1);
        sq += __shfl_xor_sync(FULLMASK, sq, 2);

        const float ssq = s * s;
        const float f   = sq * rcpf(ssq + sq) * rsqf(fmaf(1e-7f, ssq, sq));
        o0 = a0 * f; o1 = a1 * f; o2 = a2 * f; o3 = a3 * f;
    };

    pass();
    for (int it = 0; it < iters; ++it) {
        float pp[8];
#pragma unroll
        for (int m = 0; m < 8; ++m)
            pp[m] = fmaf(P[m].f.w, o3,
                    fmaf(P[m].f.z, o2,
                    fmaf(P[m].f.y, o1, P[m].f.x * o0)));
        // ring reduce (independent shfls; only the adds chain)
        const float r10 = __shfl_sync(FULLMASK, pp[6], s1, 4);
        const float r11 = __shfl_sync(FULLMASK, pp[7], s1, 4);
        const float r20 = __shfl_sync(FULLMASK, pp[4], s2, 4);
        const float r21 = __shfl_sync(FULLMASK, pp[5], s2, 4);
        const float r30 = __shfl_sync(FULLMASK, pp[2], s3, 4);
        const float r31 = __shfl_sync(FULLMASK, pp[3], s3, 4);
        const float p0 = (pp[0] + r10) + (r20 + r30);
        const float p1 = (pp[1] + r11) + (r21 + r31);

        bb0 = fmaf(p0, LOG2E, bb0);
        bb1 = fmaf(p1, LOG2E, bb1);
        pass();
    }

    if (h == 0)
        reinterpret_cast<float4*>(out)[(size_t)loc * 4 + q] =
            make_float4(o0, o1, o2, o3);
}

extern "C" void kernel_launch(void* const* d_in, const int* in_sizes, int n_in,
                              void* d_out, int out_size) {
    const float* pred = (const float*)d_in[0];
    const float* b    = (const float*)d_in[1];
    const int*   nit  = (const int*)d_in[2];
    float* out = (float*)d_out;

    const int n_loc = in_sizes[0] / 256;   // B*O*H*W
    const int ohw   = in_sizes[1] / 16;    // O*H*W
    const int ohw_mask = ((ohw & (ohw - 1)) == 0) ? (ohw - 1) : 0;

    const int warps  = (n_loc + 3) / 4;    // 4 locations per warp
    const int blocks = (warps + 7) / 8;    // 8 warps per block
    routing_kernel<<<blocks, 256>>>(pred, b, nit, out, n_loc, ohw, ohw_mask);
}

// round 9
// speedup vs baseline: 1.0620x; 1.0620x over previous
#include <cuda_runtime.h>
#include <cuda_bf16.h>

#define FULLMASK 0xFFFFFFFFu
#define LOG2E 1.4426950408889634f

using u64 = unsigned long long;

__device__ __forceinline__ u64 fma2(u64 a, u64 b, u64 c) {
    u64 d; asm("fma.rn.f32x2 %0,%1,%2,%3;" : "=l"(d) : "l"(a), "l"(b), "l"(c)); return d;
}
__device__ __forceinline__ u64 add2(u64 a, u64 b) {
    u64 d; asm("add.rn.f32x2 %0,%1,%2;" : "=l"(d) : "l"(a), "l"(b)); return d;
}
__device__ __forceinline__ u64 bcast2(float v) {
    u64 d; asm("mov.b64 %0,{%1,%1};" : "=l"(d) : "f"(v)); return d;
}
__device__ __forceinline__ float2 unpk(u64 v) {
    float2 r; asm("mov.b64 {%0,%1},%2;" : "=f"(r.x), "=f"(r.y) : "l"(v)); return r;
}
__device__ __forceinline__ float ex2f(float x) {
    float r; asm("ex2.approx.f32 %0,%1;" : "=f"(r) : "f"(x)); return r;
}
__device__ __forceinline__ float rcpf(float x) {
    float r; asm("rcp.approx.f32 %0,%1;" : "=f"(r) : "f"(x)); return r;
}
__device__ __forceinline__ float rsqf(float x) {
    float r; asm("rsqrt.approx.f32 %0,%1;" : "=f"(r) : "f"(x)); return r;
}

union Row { ulonglong2 u; float4 f; };

// Persistent warps, register double-buffered tile prefetch.
//
// Per-tile layout (unchanged from R7): 4 locations per warp, 8 lanes each.
// t = lane&7, h = t>>2 (row-half), q = t&3 (d-quad). Lane holds 8 rows of its
// half in ROTATION ORDER: slot (k,j) -> row 2*((q+k)&3)+j, cols 4q..4q+3.
// Lane OWNS rows 8h+2q, 8h+2q+1 (their logits + exponentials). Quad comm via
// width-4 shfl.idx with compile-time register slots; agree uses a ring
// reduce (partner at +k holds my rows' partials in slot (4-k)&3).
//
// b kept in log2-space; softmax 1/s never materialized (cancels in squash):
//   out = a * sq * rcp(s^2+sq) * rsq(sq + eps*s^2).  No max-subtract.
//
// Pipelining: each warp walks tiles w, w+stride, ... ; while computing the
// current tile (registers PA or PB) the next tile's 8 LDG.128 are in flight
// into the other buffer, so DRAM issue is continuous and latency hidden.
__global__ void __launch_bounds__(256, 2) routing_kernel(
    const float* __restrict__ pred,
    const float* __restrict__ b_in,
    const int*   __restrict__ nit,
    float*       __restrict__ out,
    int n_tiles, int ohw, int ohw_mask, unsigned stride)
{
    const int lane = threadIdx.x & 31;
    const int t = lane & 7;
    const int h = t >> 2;
    const int q = t & 3;
    const int g = lane >> 3;
    const int s1 = (q + 1) & 3, s2 = (q + 2) & 3, s3 = (q + 3) & 3;

    unsigned w = blockIdx.x * (blockDim.x >> 5) + (threadIdx.x >> 5);
    if (w >= (unsigned)n_tiles) return;

    const int iters = *nit;
    const ulonglong2* p4 = reinterpret_cast<const ulonglong2*>(pred);
    const int base_off = 64 * g + 32 * h + q;

    Row PA[8], PB[8];
    float bA0, bA1, bB0, bB1;

    auto load_tile = [&](Row (&P)[8], float& bb0, float& bb1, unsigned wi) {
        const ulonglong2* pp = p4 + (size_t)wi * 256;
#pragma unroll
        for (int k = 0; k < 4; ++k) {
            const int off = 8 * ((q + k) & 3);
            P[2 * k].u     = pp[base_off + off];
            P[2 * k + 1].u = pp[base_off + off + 4];
        }
        const unsigned loc = wi * 4u + g;
        const unsigned bloc = ohw_mask ? (loc & (unsigned)ohw_mask)
                                       : (loc % (unsigned)ohw);
        const float2 b2 = *reinterpret_cast<const float2*>(
            b_in + (size_t)bloc * 16 + 8 * h + 2 * q);
        bb0 = b2.x * LOG2E;
        bb1 = b2.y * LOG2E;
    };

    auto compute_tile = [&](Row (&P)[8], float bb0, float bb1, unsigned wi) {
        float o0, o1, o2, o3;

        auto pass = [&]() {
            const float e0 = ex2f(bb0), e1 = ex2f(bb1);
            float e[8];
            e[0] = e0; e[1] = e1;
            e[2] = __shfl_sync(FULLMASK, e0, s1, 4);
            e[3] = __shfl_sync(FULLMASK, e1, s1, 4);
            e[4] = __shfl_sync(FULLMASK, e0, s2, 4);
            e[5] = __shfl_sync(FULLMASK, e1, s2, 4);
            e[6] = __shfl_sync(FULLMASK, e0, s3, 4);
            e[7] = __shfl_sync(FULLMASK, e1, s3, 4);

            float s = ((e[0] + e[1]) + (e[2] + e[3])) +
                      ((e[4] + e[5]) + (e[6] + e[7]));
            s += __shfl_xor_sync(FULLMASK, s, 4);

            // weighted sum: two parallel 4-deep packed chains
            u64 x01 = 0ull, y01 = 0ull, x23 = 0ull, y23 = 0ull;
#pragma unroll
            for (int r = 0; r < 8; r += 2) {
                const u64 ea = bcast2(e[r]);
                const u64 eb = bcast2(e[r + 1]);
                x01 = fma2(ea, P[r].u.x, x01);
                x23 = fma2(ea, P[r].u.y, x23);
                y01 = fma2(eb, P[r + 1].u.x, y01);
                y23 = fma2(eb, P[r + 1].u.y, y23);
            }
            u64 a01 = add2(x01, y01);
            u64 a23 = add2(x23, y23);
            a01 = add2(a01, __shfl_xor_sync(FULLMASK, a01, 4));
            a23 = add2(a23, __shfl_xor_sync(FULLMASK, a23, 4));

            float2 lo = unpk(a01), hi = unpk(a23);
            const float a0 = lo.x, a1 = lo.y, a2 = hi.x, a3 = hi.y;

            float sq = fmaf(a3, a3, fmaf(a2, a2, fmaf(a1, a1, a0 * a0)));
            sq += __shfl_xor_sync(FULLMASK, sq, 1);
            sq += __shfl_xor_sync(FULLMASK, sq, 2);

            const float ssq = s * s;
            const float f   = sq * rcpf(ssq + sq) * rsqf(fmaf(1e-7f, ssq, sq));
            o0 = a0 * f; o1 = a1 * f; o2 = a2 * f; o3 = a3 * f;
        };

        pass();
        for (int it = 0; it < iters; ++it) {
            float pp[8];
#pragma unroll
            for (int m = 0; m < 8; ++m)
                pp[m] = fmaf(P[m].f.w, o3,
                        fmaf(P[m].f.z, o2,
                        fmaf(P[m].f.y, o1, P[m].f.x * o0)));
            const float r10 = __shfl_sync(FULLMASK, pp[6], s1, 4);
            const float r11 = __shfl_sync(FULLMASK, pp[7], s1, 4);
            const float r20 = __shfl_sync(FULLMASK, pp[4], s2, 4);
            const float r21 = __shfl_sync(FULLMASK, pp[5], s2, 4);
            const float r30 = __shfl_sync(FULLMASK, pp[2], s3, 4);
            const float r31 = __shfl_sync(FULLMASK, pp[3], s3, 4);
            const float p0 = (pp[0] + r10) + (r20 + r30);
            const float p1 = (pp[1] + r11) + (r21 + r31);

            bb0 = fmaf(p0, LOG2E, bb0);
            bb1 = fmaf(p1, LOG2E, bb1);
            pass();
        }

        if (h == 0) {
            const unsigned loc = wi * 4u + g;
            reinterpret_cast<float4*>(out)[(size_t)loc * 4 + q] =
                make_float4(o0, o1, o2, o3);
        }
    };

    // ping-pong pipeline over the grid-stride tile walk
    load_tile(PA, bA0, bA1, w);
    for (;;) {
        unsigned wn = w + stride;
        if (wn < (unsigned)n_tiles) load_tile(PB, bB0, bB1, wn);
        compute_tile(PA, bA0, bA1, w);
        if (wn >= (unsigned)n_tiles) break;
        w = wn;

        wn = w + stride;
        if (wn < (unsigned)n_tiles) load_tile(PA, bA0, bA1, wn);
        compute_tile(PB, bB0, bB1, w);
        if (wn >= (unsigned)n_tiles) break;
        w = wn;
    }
}

extern "C" void kernel_launch(void* const* d_in, const int* in_sizes, int n_in,
                              void* d_out, int out_size) {
    const float* pred = (const float*)d_in[0];
    const float* b    = (const float*)d_in[1];
    const int*   nit  = (const int*)d_in[2];
    float* out = (float*)d_out;

    const int n_loc = in_sizes[0] / 256;   // B*O*H*W
    const int ohw   = in_sizes[1] / 16;    // O*H*W
    const int ohw_mask = ((ohw & (ohw - 1)) == 0) ? (ohw - 1) : 0;

    const int n_tiles = (n_loc + 3) / 4;   // 4 locations per warp-tile
    const int blocks  = 296;               // 2 resident blocks x 148 SMs
    const unsigned stride = (unsigned)blocks * 8u;  // warps in grid
    routing_kernel<<<blocks, 256>>>(pred, b, nit, out,
                                    n_tiles, ohw, ohw_mask, stride);
}

// round 10
// speedup vs baseline: 1.1717x; 1.1032x over previous
#include <cuda_runtime.h>
#include <cuda_bf16.h>

#define FULLMASK 0xFFFFFFFFu
#define LOG2E 1.4426950408889634f

__device__ __forceinline__ float ex2f(float x) {
    float r; asm("ex2.approx.f32 %0,%1;" : "=f"(r) : "f"(x)); return r;
}
__device__ __forceinline__ float rcpf(float x) {
    float r; asm("rcp.approx.f32 %0,%1;" : "=f"(r) : "f"(x)); return r;
}
__device__ __forceinline__ float rsqf(float x) {
    float r; asm("rsqrt.approx.f32 %0,%1;" : "=f"(r) : "f"(x)); return r;
}

// Decomposition: 8 locations per warp, 4 lanes per location.
// g = lane>>2 (location in warp), q = lane&3 (d-quad).
// Lane holds ALL 16 rows of its location, columns d = 4q..4q+3  (P[16] float4)
//   -> the weighted sum over i is fully lane-local (NO cross-lane reduce).
// Lane OWNS rows 4q..4q+3: their logits bb[4] and exponentials.
// Cross-lane data exchange goes through warp-private shared memory
// (warp-synchronous: only __syncwarp between STS and LDS):
//   pass : owner STS.128 its 4 e -> all 4 lanes LDS.128 x4 (broadcast reads)
//   agree: lane STS.128 x4 its 16 partial dots -> owner LDS.128 x4 gathers
//          the 4 partials of each of its own rows.
// Only 2 SHFLs remain per pass (|a|^2 quad reduction).
//
// b kept in log2-space; softmax 1/s never materialized (cancels in squash):
//   out = a * sq * rcp(s^2+sq) * rsq(sq + eps*s^2).   No max-subtract needed.
__global__ void __launch_bounds__(256, 2) routing_kernel(
    const float* __restrict__ pred,
    const float* __restrict__ b_in,
    const int*   __restrict__ nit,
    float*       __restrict__ out,
    int n_loc, int ohw, int ohw_mask)
{
    // padded strides (20 floats = 80B) keep LDS/STS bank groups distinct
    __shared__ __align__(16) float e_sm[8][8][20];      // [warp][g][16 used]
    __shared__ __align__(16) float pp_sm[8][8][4][20];  // [warp][g][q][16 used]

    const int lane = threadIdx.x & 31;
    const int wid  = threadIdx.x >> 5;
    const int g = lane >> 2;
    const int q = lane & 3;
    const unsigned w = blockIdx.x * (blockDim.x >> 5) + wid;
    if (w * 8u >= (unsigned)n_loc) return;      // warp-uniform guard
    const unsigned loc = w * 8u + g;

    // ---- pred tile: 16 LDG.128 (8 KB per warp), fully sector-efficient ----
    const float4* p4 = reinterpret_cast<const float4*>(pred);
    const int pbase = (int)(w * 512u) + g * 64 + q;
    float4 P[16];
#pragma unroll
    for (int k = 0; k < 16; ++k)
        P[k] = p4[pbase + 4 * k];

    // ---- own rows' logits: one LDG.128 (log2-space) ----
    const unsigned bloc = ohw_mask ? (loc & (unsigned)ohw_mask)
                                   : (loc % (unsigned)ohw);
    float bb[4];
    {
        const float4 bv = *reinterpret_cast<const float4*>(
            b_in + (size_t)bloc * 16 + 4 * q);
        bb[0] = bv.x * LOG2E; bb[1] = bv.y * LOG2E;
        bb[2] = bv.z * LOG2E; bb[3] = bv.w * LOG2E;
    }

    const int iters = *nit;
    float o0, o1, o2, o3;

    float* eg  = &e_sm[wid][g][0];
    float* ppg = &pp_sm[wid][g][0][0];

    auto pass = [&]() {
        // owner exponentials -> smem broadcast
        *reinterpret_cast<float4*>(eg + 4 * q) =
            make_float4(ex2f(bb[0]), ex2f(bb[1]), ex2f(bb[2]), ex2f(bb[3]));
        __syncwarp();
        const float4 E0 = *reinterpret_cast<const float4*>(eg);
        const float4 E1 = *reinterpret_cast<const float4*>(eg + 4);
        const float4 E2 = *reinterpret_cast<const float4*>(eg + 8);
        const float4 E3 = *reinterpret_cast<const float4*>(eg + 12);
        const float e[16] = {E0.x,E0.y,E0.z,E0.w, E1.x,E1.y,E1.z,E1.w,
                             E2.x,E2.y,E2.z,E2.w, E3.x,E3.y,E3.z,E3.w};

        float s = ((e[0]+e[1])+(e[2]+e[3])) + ((e[4]+e[5])+(e[6]+e[7]))
                + ((e[8]+e[9])+(e[10]+e[11])) + ((e[12]+e[13])+(e[14]+e[15]));

        // fully local weighted sum over all 16 rows (two chains per column)
        float a0 = e[0]*P[0].x, a1 = e[0]*P[0].y;
        float a2 = e[0]*P[0].z, a3 = e[0]*P[0].w;
        float c0 = e[8]*P[8].x, c1 = e[8]*P[8].y;
        float c2 = e[8]*P[8].z, c3 = e[8]*P[8].w;
#pragma unroll
        for (int r = 1; r < 8; ++r) {
            a0 = fmaf(e[r], P[r].x, a0);
            a1 = fmaf(e[r], P[r].y, a1);
            a2 = fmaf(e[r], P[r].z, a2);
            a3 = fmaf(e[r], P[r].w, a3);
            c0 = fmaf(e[r+8], P[r+8].x, c0);
            c1 = fmaf(e[r+8], P[r+8].y, c1);
            c2 = fmaf(e[r+8], P[r+8].z, c2);
            c3 = fmaf(e[r+8], P[r+8].w, c3);
        }
        a0 += c0; a1 += c1; a2 += c2; a3 += c3;

        // |a|^2 over 16 d: local quad + 2-shfl reduce across the 4 q-lanes
        float sq = fmaf(a3, a3, fmaf(a2, a2, fmaf(a1, a1, a0 * a0)));
        sq += __shfl_xor_sync(FULLMASK, sq, 1);
        sq += __shfl_xor_sync(FULLMASK, sq, 2);

        const float s2 = s * s;
        const float f  = sq * rcpf(s2 + sq) * rsqf(fmaf(1e-7f, s2, sq));
        o0 = a0 * f; o1 = a1 * f; o2 = a2 * f; o3 = a3 * f;
    };

    pass();
    for (int it = 0; it < iters; ++it) {
        // partial dots for ALL 16 rows (my 4 columns), to smem
#pragma unroll
        for (int k = 0; k < 4; ++k) {
            float4 v;
            v.x = fmaf(P[4*k+0].w, o3, fmaf(P[4*k+0].z, o2,
                  fmaf(P[4*k+0].y, o1, P[4*k+0].x * o0)));
            v.y = fmaf(P[4*k+1].w, o3, fmaf(P[4*k+1].z, o2,
                  fmaf(P[4*k+1].y, o1, P[4*k+1].x * o0)));
            v.z = fmaf(P[4*k+2].w, o3, fmaf(P[4*k+2].z, o2,
                  fmaf(P[4*k+2].y, o1, P[4*k+2].x * o0)));
            v.w = fmaf(P[4*k+3].w, o3, fmaf(P[4*k+3].z, o2,
                  fmaf(P[4*k+3].y, o1, P[4*k+3].x * o0)));
            *reinterpret_cast<float4*>(ppg + q * 20 + 4 * k) = v;
        }
        __syncwarp();
        // gather the 4 columns' partials of MY rows (4q..4q+3)
        const float4 t0 = *reinterpret_cast<const float4*>(ppg + 0  * 20 + 4 * q);
        const float4 t1 = *reinterpret_cast<const float4*>(ppg + 1  * 20 + 4 * q);
        const float4 t2 = *reinterpret_cast<const float4*>(ppg + 2  * 20 + 4 * q);
        const float4 t3 = *reinterpret_cast<const float4*>(ppg + 3  * 20 + 4 * q);
        bb[0] = fmaf((t0.x + t1.x) + (t2.x + t3.x), LOG2E, bb[0]);
        bb[1] = fmaf((t0.y + t1.y) + (t2.y + t3.y), LOG2E, bb[1]);
        bb[2] = fmaf((t0.z + t1.z) + (t2.z + t3.z), LOG2E, bb[2]);
        bb[3] = fmaf((t0.w + t1.w) + (t2.w + t3.w), LOG2E, bb[3]);
        pass();
    }

    // every lane stores its d-quad: 8 loc x 64B contiguous per warp
    *reinterpret_cast<float4*>(out + (size_t)loc * 16 + 4 * q) =
        make_float4(o0, o1, o2, o3);
}

extern "C" void kernel_launch(void* const* d_in, const int* in_sizes, int n_in,
                              void* d_out, int out_size) {
    const float* pred = (const float*)d_in[0];
    const float* b    = (const float*)d_in[1];
    const int*   nit  = (const int*)d_in[2];
    float* out = (float*)d_out;

    const int n_loc = in_sizes[0] / 256;   // B*O*H*W
    const int ohw   = in_sizes[1] / 16;    // O*H*W
    const int ohw_mask = ((ohw & (ohw - 1)) == 0) ? (ohw - 1) : 0;

    const int warps  = (n_loc + 7) / 8;    // 8 locations per warp
    const int blocks = (warps + 7) / 8;    // 8 warps per block
    routing_kernel<<<blocks, 256>>>(pred, b, nit, out, n_loc, ohw, ohw_mask);
}